// round 15
// baseline (speedup 1.0000x reference)
#include <cuda_runtime.h>
#include <math.h>
#include <stdint.h>

// Problem constants
#define BB   8
#define SS   128
#define DD   1024
#define HH   4096
#define MM   (BB*SS)          // 1024
#define KSEL (256*128)        // 32768 = TOPK*S
#define AMB_CAP 32768

// ---------------- scratch (device globals; no allocation) ----------------
__device__ float g_buf[MM*HH];        // fp32 gate hidden (refine ground truth)
__device__ float score_buf[MM*HH];    // scores; reused as split-K scratch later
// packed bf16 plane buffers: [rows][K/2] u32 words
__device__ uint32_t w2h_buf[(size_t)HH*HH/2];
__device__ uint32_t xh_buf[MM*DD/2],  xm_buf[MM*DD/2],  xl_buf[MM*DD/2];
__device__ uint32_t w1h_buf[HH*DD/2], w1m_buf[HH*DD/2], w1l_buf[HH*DD/2];
__device__ uint32_t uph_buf[HH*DD/2], upl_buf[HH*DD/2];
__device__ uint32_t uch_buf[HH*DD/2], ucl_buf[HH*DD/2];
__device__ uint32_t dwh_buf[DD*HH/2], dwl_buf[DD*HH/2];
__device__ uint32_t gh_buf[MM*HH/2];
__device__ uint32_t hh_buf[MM*HH/2],  hl_buf[MM*HH/2];

__device__ unsigned int hist_buf[BB][256];
__device__ unsigned int prefix_buf[BB];
__device__ unsigned int remain_buf[BB];
__device__ float thr_buf[BB];
__device__ int   cin_buf[BB];
__device__ int   ambcnt_buf[BB];
__device__ int   take_buf[BB];
__device__ unsigned int amb_idx[BB][AMB_CAP];
__device__ float amb_val[BB][AMB_CAP];
__device__ unsigned char sel_buf[BB*HH];

// ---------------- small helpers ----------------
__device__ __forceinline__ unsigned int fkey(float f) {
    unsigned int u = __float_as_uint(f);
    return u ^ ((u >> 31) ? 0xFFFFFFFFu : 0x80000000u);
}
__device__ __forceinline__ float key2f(unsigned int k) {
    unsigned int u = (k & 0x80000000u) ? (k ^ 0x80000000u) : ~k;
    return __uint_as_float(u);
}
__device__ __forceinline__ uint32_t smem_u32(const void* p) {
    uint32_t a;
    asm("{ .reg .u64 t; cvta.to.shared.u64 t, %1; cvt.u32.u64 %0, t; }" : "=r"(a) : "l"(p));
    return a;
}
__device__ __forceinline__ void cpasync16(uint32_t saddr, const void* g) {
    asm volatile("cp.async.cg.shared.global [%0], [%1], 16;" :: "r"(saddr), "l"(g));
}
__device__ __forceinline__ void ldmx4(uint32_t& r0, uint32_t& r1, uint32_t& r2,
                                      uint32_t& r3, uint32_t addr) {
    asm volatile("ldmatrix.sync.aligned.m8n8.x4.shared.b16 {%0,%1,%2,%3}, [%4];"
                 : "=r"(r0), "=r"(r1), "=r"(r2), "=r"(r3) : "r"(addr));
}
__device__ __forceinline__ void mma16bf(float* d, const uint32_t* a, const uint32_t* b) {
    asm volatile(
        "mma.sync.aligned.m16n8k16.row.col.f32.bf16.bf16.f32 "
        "{%0,%1,%2,%3}, {%4,%5,%6,%7}, {%8,%9}, {%0,%1,%2,%3};"
        : "+f"(d[0]), "+f"(d[1]), "+f"(d[2]), "+f"(d[3])
        : "r"(a[0]), "r"(a[1]), "r"(a[2]), "r"(a[3]), "r"(b[0]), "r"(b[1]));
}
__device__ __forceinline__ uint32_t pack_bf16(float v0, float v1) {
    uint32_t h;
    asm("cvt.rn.bf16x2.f32 %0, %1, %2;" : "=r"(h) : "f"(v1), "f"(v0));
    return h;
}
__device__ __forceinline__ void unpack_bf16pair(uint32_t w, float& f0, float& f1) {
    f0 = __uint_as_float(w << 16);
    f1 = __uint_as_float(w & 0xFFFF0000u);
}
__device__ __forceinline__ void pack_split_bf16(float v0, float v1,
                                                uint32_t& hi, uint32_t& lo) {
    hi = pack_bf16(v0, v1);
    float h0, h1;
    unpack_bf16pair(hi, h0, h1);
    lo = pack_bf16(v0 - h0, v1 - h1);
}
__device__ __forceinline__ void pack_split3_bf16(float v0, float v1,
                                                 uint32_t& hi, uint32_t& mi, uint32_t& lo) {
    hi = pack_bf16(v0, v1);
    float h0, h1;
    unpack_bf16pair(hi, h0, h1);
    float r0 = v0 - h0, r1 = v1 - h1;
    mi = pack_bf16(r0, r1);
    float m0, m1;
    unpack_bf16pair(mi, m0, m1);
    lo = pack_bf16(r0 - m0, r1 - m1);
}
// EPI: 0 +bias; 1 relu(+bias); 2 select-bias+GELU; 3 raw (split-K partial)
template<int EPI>
__device__ __forceinline__ float epi_apply(float x, int cc, bool se,
                                           const float* bias_p, const float* bias_c) {
    if (EPI == 0) {
        x += bias_p[cc];
    } else if (EPI == 1) {
        x += bias_p[cc];
        x = fmaxf(x, 0.0f);
    } else if (EPI == 2) {
        x += se ? bias_p[cc] : bias_c[cc];
        x = 0.5f * x * (1.0f + erff(x * 0.70710678118654752f));
    }
    return x;
}

// ---------------- decomposition kernels ----------------
__global__ void decomp_split3_kernel(const float2* __restrict__ src,
                                     uint32_t* __restrict__ h, uint32_t* __restrict__ m,
                                     uint32_t* __restrict__ l, int n2) {
    int i = blockIdx.x * blockDim.x + threadIdx.x;
    if (i >= n2) return;
    float2 v = src[i];
    uint32_t hh, mm, ll;
    pack_split3_bf16(v.x, v.y, hh, mm, ll);
    h[i] = hh; m[i] = mm; l[i] = ll;
}
__global__ void decomp_split_kernel(const float2* __restrict__ src,
                                    uint32_t* __restrict__ hi,
                                    uint32_t* __restrict__ lo, int n2) {
    int i = blockIdx.x * blockDim.x + threadIdx.x;
    if (i >= n2) return;
    float2 v = src[i];
    uint32_t h, l;
    pack_split_bf16(v.x, v.y, h, l);
    hi[i] = h; lo[i] = l;
}
__global__ void decomp_hi_kernel(const float2* __restrict__ src,
                                 uint32_t* __restrict__ hi, int n2) {
    int i = blockIdx.x * blockDim.x + threadIdx.x;
    if (i >= n2) return;
    float2 v = src[i];
    hi[i] = pack_bf16(v.x, v.y);
}

// ---------------- split-K combine: out = p0 + p1 + bias ----------------
__global__ void combine_kernel(const float4* __restrict__ p0,
                               const float4* __restrict__ p1,
                               const float* __restrict__ bias,
                               float4* __restrict__ out, int n4) {
    int i = blockIdx.x * blockDim.x + threadIdx.x;
    if (i >= n4) return;
    float4 a = p0[i], b = p1[i];
    const float4 bb = *(const float4*)(bias + ((i * 4) & (DD - 1)));
    a.x += b.x + bb.x; a.y += b.y + bb.y;
    a.z += b.z + bb.z; a.w += b.w + bb.w;
    out[i] = a;
}

// ---------------- init ----------------
__global__ void init_hist() {
    int t = blockIdx.x * blockDim.x + threadIdx.x;
    if (t < BB * 256) ((unsigned int*)hist_buf)[t] = 0u;
}
__global__ void init_misc() {
    int t = threadIdx.x;
    if (t < BB) {
        prefix_buf[t] = 0u; remain_buf[t] = KSEL;
        cin_buf[t] = 0; ambcnt_buf[t] = 0; take_buf[t] = 0;
    }
}
__global__ void init_sel() {
    int t = blockIdx.x * blockDim.x + threadIdx.x;
    ((unsigned int*)sel_buf)[t] = 0u;
}

// ---------------- radix select (4 passes -> exact 32-bit threshold) --------
__global__ void __launch_bounds__(256) hist_pass(int pass) {
    __shared__ unsigned int sh[256];
    int b = blockIdx.y;
    for (int i = threadIdx.x; i < 256; i += blockDim.x) sh[i] = 0;
    __syncthreads();
    unsigned int pre = prefix_buf[b];
    int shift = 24 - 8 * pass;
    const float4* sb = (const float4*)(score_buf + (size_t)b * SS * HH);
    int total = SS * HH / 4;
    for (int i = blockIdx.x * blockDim.x + threadIdx.x; i < total;
         i += gridDim.x * blockDim.x) {
        float4 v = sb[i];
        unsigned int k0 = fkey(v.x), k1 = fkey(v.y), k2 = fkey(v.z), k3 = fkey(v.w);
        if (pass == 0) {
            atomicAdd(&sh[(k0 >> shift) & 0xFF], 1u);
            atomicAdd(&sh[(k1 >> shift) & 0xFF], 1u);
            atomicAdd(&sh[(k2 >> shift) & 0xFF], 1u);
            atomicAdd(&sh[(k3 >> shift) & 0xFF], 1u);
        } else {
            if ((k0 >> (shift + 8)) == pre) atomicAdd(&sh[(k0 >> shift) & 0xFF], 1u);
            if ((k1 >> (shift + 8)) == pre) atomicAdd(&sh[(k1 >> shift) & 0xFF], 1u);
            if ((k2 >> (shift + 8)) == pre) atomicAdd(&sh[(k2 >> shift) & 0xFF], 1u);
            if ((k3 >> (shift + 8)) == pre) atomicAdd(&sh[(k3 >> shift) & 0xFF], 1u);
        }
    }
    __syncthreads();
    for (int i = threadIdx.x; i < 256; i += blockDim.x)
        if (sh[i]) atomicAdd(&hist_buf[b][i], sh[i]);
}

__global__ void scan_pass() {
    int t = threadIdx.x;
    if (t < BB) {
        unsigned int r = remain_buf[t];
        unsigned int cum = 0;
        for (int bin = 255; bin >= 0; bin--) {
            unsigned int c = hist_buf[t][bin];
            if (cum + c >= r) {
                prefix_buf[t] = (prefix_buf[t] << 8) | (unsigned int)bin;
                remain_buf[t] = r - cum;
                break;
            }
            cum += c;
        }
    }
    __syncthreads();
    for (int i = threadIdx.x; i < BB * 256; i += blockDim.x)
        ((unsigned int*)hist_buf)[i] = 0u;
}

__global__ void thr_kernel() {
    int t = threadIdx.x;
    if (t < BB) thr_buf[t] = key2f(prefix_buf[t]);   // exact bf16-score kth value
}

// ---------------- band + refine + select ----------------
__global__ void __launch_bounds__(256) band_kernel() {
    int b = blockIdx.y;
    float T = thr_buf[b];
    float del = fmaxf(1e-2f, 1e-2f * fabsf(T));
    float Thi = T + del, Tlo = T - del;
    __shared__ int scnt;
    if (threadIdx.x == 0) scnt = 0;
    __syncthreads();
    int i = blockIdx.x * blockDim.x + threadIdx.x;
    const float4* sb = (const float4*)(score_buf + (size_t)b * SS * HH);
    float4 v = sb[i];
    float f[4] = { v.x, v.y, v.z, v.w };
    int base = i * 4;
    #pragma unroll
    for (int q = 0; q < 4; q++) {
        if (f[q] > Thi) {
            atomicAdd(&scnt, 1);
            sel_buf[b * HH + ((base + q) & (HH - 1))] = 1;
        } else if (f[q] > Tlo) {
            int p = atomicAdd(&ambcnt_buf[b], 1);
            if (p < AMB_CAP) amb_idx[b][p] = (unsigned int)(base + q);
        }
    }
    __syncthreads();
    if (threadIdx.x == 0 && scnt) atomicAdd(&cin_buf[b], scnt);
}

__global__ void __launch_bounds__(256) refine_kernel(const float* __restrict__ w2,
                                                     const float* __restrict__ b2) {
    int b = blockIdx.y;
    int n = min(ambcnt_buf[b], AMB_CAP);
    int wid = (blockIdx.x * blockDim.x + threadIdx.x) >> 5;
    int lid = threadIdx.x & 31;
    int nwarps = (gridDim.x * blockDim.x) >> 5;
    for (int it = wid; it < n; it += nwarps) {
        unsigned int idx = amb_idx[b][it];
        int h = idx & (HH - 1);
        const float* grow = g_buf + (size_t)b * SS * HH + (idx - h);
        const float* wrow = w2 + (size_t)h * HH;
        float s = 0.0f;
        for (int j = lid * 4; j < HH; j += 128) {
            float4 gg = *(const float4*)(grow + j);
            float4 ww = *(const float4*)(wrow + j);
            s += gg.x * ww.x + gg.y * ww.y + gg.z * ww.z + gg.w * ww.w;
        }
        #pragma unroll
        for (int o = 16; o > 0; o >>= 1)
            s += __shfl_xor_sync(0xFFFFFFFFu, s, o);
        if (lid == 0) amb_val[b][it] = s + b2[h];
    }
}

__global__ void __launch_bounds__(256) select_kernel() {
    int b = blockIdx.x;
    int n = min(ambcnt_buf[b], AMB_CAP);
    int slots = KSEL - cin_buf[b];
    if (slots < 0) slots = 0;
    if (slots > n) slots = n;
    __shared__ int red[256];

    unsigned int lo = 0u, hi = 0xFFFFFFFFu;
    while (lo < hi) {
        unsigned int mid = lo + ((hi - lo) >> 1) + 1u;
        int c = 0;
        for (int i = threadIdx.x; i < n; i += 256)
            c += (fkey(amb_val[b][i]) >= mid) ? 1 : 0;
        red[threadIdx.x] = c;
        __syncthreads();
        for (int o = 128; o > 0; o >>= 1) {
            if (threadIdx.x < o) red[threadIdx.x] += red[threadIdx.x + o];
            __syncthreads();
        }
        if (red[0] >= slots) lo = mid; else hi = mid - 1u;
        __syncthreads();
    }
    const unsigned int Kstar = lo;
    int c = 0;
    for (int i = threadIdx.x; i < n; i += 256)
        c += (fkey(amb_val[b][i]) > Kstar) ? 1 : 0;
    red[threadIdx.x] = c;
    __syncthreads();
    for (int o = 128; o > 0; o >>= 1) {
        if (threadIdx.x < o) red[threadIdx.x] += red[threadIdx.x + o];
        __syncthreads();
    }
    const int need = slots - red[0];
    for (int i = threadIdx.x; i < n; i += 256) {
        unsigned int k = fkey(amb_val[b][i]);
        bool m = false;
        if (k > Kstar) m = true;
        else if (k == Kstar) {
            int p = atomicAdd(&take_buf[b], 1);
            if (p < need) m = true;
        }
        if (m) sel_buf[b * HH + (amb_idx[b][i] & (HH - 1))] = 1;
    }
}

// ---------------- bf16 NT GEMM: cp.async (2-stage, R9 loop) + ldmatrix ------
// A,B pre-packed bf16 planes in GMEM as [rows][K/2] u32 words.
// NT: 1 / 3 / 6 -> plane count PA = 1 / 2 / 3; MMA set: (i,j) with i+j < PA.
// MT: m-subtiles per warp (4 -> 128-row CTA, 2 -> 64-row CTA).
// OUT: 0 = fp32 C; 1 = packed bf16 hi/lo; 2 = fp32 C + bf16 hi.
// kspan: K-range handled by this z-slice (kspan == K when not split).
// part_elems: output offset per blockIdx.z (split-K partial buffers).
#define LDBW 20   // u32 words per SMEM row (80B stride)

template<int EPI, bool SELB, int NT, int MT, int OUT>
__global__ void __launch_bounds__(256, (NT == 1) ? (MT == 2 ? 3 : 2) : (MT == 2 ? 2 : 1))
gemm_bfx(const uint32_t* __restrict__ A0, const uint32_t* __restrict__ A1,
         const uint32_t* __restrict__ A2,
         const uint32_t* __restrict__ B0p, const uint32_t* __restrict__ B1p,
         const uint32_t* __restrict__ B2p,
         const uint32_t* __restrict__ B0c, const uint32_t* __restrict__ B1c,
         const float* __restrict__ bias_p, const float* __restrict__ bias_c,
         float* __restrict__ Cf, uint32_t* __restrict__ Ch, uint32_t* __restrict__ Cl,
         int N, int K, int kspan, size_t part_elems)
{
    constexpr int PA = (NT == 1) ? 1 : (NT == 3) ? 2 : 3;
    constexpr int CTA_ROWS = MT * 32;
    constexpr int A_TILE_U = CTA_ROWS * LDBW;
    constexpr int B_TILE_U = 128 * LDBW;
    constexpr int STAGE_U  = PA * (A_TILE_U + B_TILE_U);
    constexpr int AUPT     = (CTA_ROWS * 4) / 256;

    extern __shared__ uint32_t smu[];
    const uint32_t sbase = smem_u32(smu);

    const int tid = threadIdx.x;
    const int wid = tid >> 5;
    const int lid = tid & 31;
    const int g   = lid >> 2;
    const int cth = lid & 3;
    const int wm  = wid & 1;
    const int wn  = wid >> 1;
    const int mBase = blockIdx.y * CTA_ROWS;
    const int nBase = blockIdx.x * 128;
    const int KW = K >> 1;
    const int koffw = blockIdx.z * (kspan >> 1);     // word offset into K
    float* Cfp = Cf + (size_t)blockIdx.z * part_elems;

    const uint32_t* Ag[3] = { A0, A1, A2 };
    const uint32_t* Bg[3] = { B0p, B1p, B2p };

    // batch = row block / SS (CTA rows never straddle a batch: 64 | 128)
    const unsigned char* selrow = SELB ? (sel_buf + (size_t)(mBase >> 7) * HH)
                                       : (const unsigned char*)0;

    float acc[MT][4][4];
    #pragma unroll
    for (int a = 0; a < MT; a++)
        #pragma unroll
        for (int b = 0; b < 4; b++)
            #pragma unroll
            for (int q = 0; q < 4; q++) acc[a][b][q] = 0.0f;

    const int nslab = kspan >> 5;

    auto issue = [&](int s) {
        const int stg = s & 1;
        const int kw = koffw + s * 16;
        const uint32_t st = sbase + (uint32_t)stg * (STAGE_U * 4);
        #pragma unroll
        for (int t = 0; t < AUPT; t++) {
            const int u = t * 256 + tid;
            const int row = u >> 2, ch = u & 3;
            const uint32_t so = (uint32_t)(row * LDBW + ch * 4) * 4;
            const size_t go = (size_t)(mBase + row) * KW + kw + ch * 4;
            #pragma unroll
            for (int p = 0; p < PA; p++)
                cpasync16(st + (uint32_t)p * (A_TILE_U * 4) + so, Ag[p] + go);
        }
        #pragma unroll
        for (int t = 0; t < 2; t++) {
            const int u = t * 256 + tid;
            const int row = u >> 2, ch = u & 3;
            const int nrow = nBase + row;
            const uint32_t so = (uint32_t)(row * LDBW + ch * 4) * 4;
            const size_t go = (size_t)nrow * KW + kw + ch * 4;
            const uint32_t bb = st + (uint32_t)(PA * A_TILE_U) * 4;
            if (SELB) {
                const bool se = selrow[nrow] != 0;
                cpasync16(bb + so, (se ? B0p : B0c) + go);
                if (PA >= 2)
                    cpasync16(bb + (uint32_t)(B_TILE_U * 4) + so, (se ? B1p : B1c) + go);
            } else {
                #pragma unroll
                for (int p = 0; p < PA; p++)
                    cpasync16(bb + (uint32_t)p * (B_TILE_U * 4) + so, Bg[p] + go);
            }
        }
        asm volatile("cp.async.commit_group;" ::: "memory");
    };

    auto compute = [&](int stg) {
        const uint32_t st = sbase + (uint32_t)stg * (STAGE_U * 4);
        #pragma unroll
        for (int ks = 0; ks < 2; ks++) {
            const int pc0 = ks * 8;
            uint32_t bfr[PA][4][2];
            #pragma unroll
            for (int p = 0; p < PA; p++) {
                const uint32_t BS = st + (uint32_t)(PA * A_TILE_U + p * B_TILE_U) * 4;
                #pragma unroll
                for (int nip = 0; nip < 2; nip++) {
                    const int nb2 = wn * 32 + nip * 16;
                    const uint32_t ba = (uint32_t)((nb2 + (lid & 7) + ((lid >> 4) & 1) * 8)
                                        * LDBW + pc0) * 4 + ((lid >> 3) & 1) * 16;
                    ldmx4(bfr[p][2*nip][0], bfr[p][2*nip][1],
                          bfr[p][2*nip+1][0], bfr[p][2*nip+1][1], BS + ba);
                }
            }
            #pragma unroll
            for (int mi = 0; mi < MT; mi++) {
                const int rb = wm * (MT * 16) + mi * 16;
                const uint32_t aoff = (uint32_t)((rb + (lid & 15)) * LDBW + pc0) * 4
                                      + (lid >> 4) * 16;
                uint32_t afr[PA][4];
                #pragma unroll
                for (int p = 0; p < PA; p++)
                    ldmx4(afr[p][0], afr[p][1], afr[p][2], afr[p][3],
                          st + (uint32_t)p * (A_TILE_U * 4) + aoff);
                #pragma unroll
                for (int ni = 0; ni < 4; ni++) {
                    #pragma unroll
                    for (int o = PA - 1; o >= 0; o--)      // o = i + j
                        #pragma unroll
                        for (int i = 0; i <= o; i++)
                            mma16bf(acc[mi][ni], afr[i], bfr[o - i][ni]);
                }
            }
        }
    };

    // R9 proven loop: issue-before-wait, 2 stages, 2 syncs
    issue(0);
    for (int s = 0; s < nslab; s++) {
        if (s + 1 < nslab) {
            issue(s + 1);
            asm volatile("cp.async.wait_group 1;" ::: "memory");
        } else {
            asm volatile("cp.async.wait_group 0;" ::: "memory");
        }
        __syncthreads();
        compute(s & 1);
        __syncthreads();
    }

    #pragma unroll
    for (int mi = 0; mi < MT; mi++) {
        const int r0 = mBase + wm * (MT * 16) + mi * 16 + g;
        #pragma unroll
        for (int ni = 0; ni < 4; ni++) {
            const int col = nBase + wn * 32 + ni * 8 + 2 * cth;
            float v[4] = { acc[mi][ni][0], acc[mi][ni][1],
                           acc[mi][ni][2], acc[mi][ni][3] };
            #pragma unroll
            for (int q = 0; q < 4; q++) {
                const int cc = col + (q & 1);
                const bool se = SELB ? (selrow[cc] != 0) : false;
                v[q] = epi_apply<EPI>(v[q], cc, se, bias_p, bias_c);
            }
            if (OUT == 0 || OUT == 2) {
                *(float2*)(Cfp + (size_t)r0 * N + col)       = make_float2(v[0], v[1]);
                *(float2*)(Cfp + (size_t)(r0 + 8) * N + col) = make_float2(v[2], v[3]);
            }
            if (OUT == 1) {
                uint32_t h, l;
                pack_split_bf16(v[0], v[1], h, l);
                Ch[((size_t)r0 * N + col) >> 1] = h;
                Cl[((size_t)r0 * N + col) >> 1] = l;
                pack_split_bf16(v[2], v[3], h, l);
                Ch[((size_t)(r0 + 8) * N + col) >> 1] = h;
                Cl[((size_t)(r0 + 8) * N + col) >> 1] = l;
            }
            if (OUT == 2) {
                Ch[((size_t)r0 * N + col) >> 1]       = pack_bf16(v[0], v[1]);
                Ch[((size_t)(r0 + 8) * N + col) >> 1] = pack_bf16(v[2], v[3]);
            }
        }
    }
}

// SMEM sizes (bytes, 2 stages)
#define SMEM_G1 (2 * 3 * ((64*LDBW) + (128*LDBW)) * 4)      // NT=6, MT=2: 92KB -> 2 CTA/SM
#define SMEM_G2 (2 * 1 * ((64*LDBW) + (128*LDBW)) * 4)      // NT=1, MT=2: 31KB -> 3 CTA/SM
#define SMEM_G5 (2 * 2 * ((64*LDBW) + (128*LDBW)) * 4)      // NT=3, MT=2: 60KB -> 2 CTA/SM
#define SMEM_G6 (2 * 2 * ((64*LDBW) + (128*LDBW)) * 4)      // NT=3, MT=2: 60KB -> 2 CTA/SM

// ---------------- launch ----------------
extern "C" void kernel_launch(void* const* d_in, const int* in_sizes, int n_in,
                              void* d_out, int out_size)
{
    const float* x         = (const float*)d_in[0];   // [B,S,D]
    const float* up_prev_w = (const float*)d_in[1];   // [H,D]
    const float* up_prev_b = (const float*)d_in[2];   // [H]
    const float* up_curr_w = (const float*)d_in[3];   // [H,D]
    const float* up_curr_b = (const float*)d_in[4];   // [H]
    const float* gate_w1   = (const float*)d_in[5];   // [H,D]
    const float* gate_b1   = (const float*)d_in[6];   // [H]
    const float* gate_w2   = (const float*)d_in[7];   // [H,H]
    const float* gate_b2   = (const float*)d_in[8];   // [H]
    const float* down_w    = (const float*)d_in[9];   // [D,H]
    const float* down_b    = (const float*)d_in[10];  // [D]
    float* out = (float*)d_out;                       // [B,S,D]

    float *gp, *sp;
    uint32_t *w2h, *xh, *xm, *xl, *w1h, *w1m, *w1l;
    uint32_t *uph, *upl, *uch, *ucl, *dwh, *dwl, *ghp, *hhp, *hlp;
    cudaGetSymbolAddress((void**)&gp,  g_buf);
    cudaGetSymbolAddress((void**)&sp,  score_buf);
    cudaGetSymbolAddress((void**)&w2h, w2h_buf);
    cudaGetSymbolAddress((void**)&xh,  xh_buf);
    cudaGetSymbolAddress((void**)&xm,  xm_buf);
    cudaGetSymbolAddress((void**)&xl,  xl_buf);
    cudaGetSymbolAddress((void**)&w1h, w1h_buf);
    cudaGetSymbolAddress((void**)&w1m, w1m_buf);
    cudaGetSymbolAddress((void**)&w1l, w1l_buf);
    cudaGetSymbolAddress((void**)&uph, uph_buf);  cudaGetSymbolAddress((void**)&upl, upl_buf);
    cudaGetSymbolAddress((void**)&uch, uch_buf);  cudaGetSymbolAddress((void**)&ucl, ucl_buf);
    cudaGetSymbolAddress((void**)&dwh, dwh_buf);  cudaGetSymbolAddress((void**)&dwl, dwl_buf);
    cudaGetSymbolAddress((void**)&ghp, gh_buf);
    cudaGetSymbolAddress((void**)&hhp, hh_buf);   cudaGetSymbolAddress((void**)&hlp, hl_buf);

    cudaFuncSetAttribute((const void*)gemm_bfx<1, false, 6, 2, 2>, cudaFuncAttributeMaxDynamicSharedMemorySize, SMEM_G1);
    cudaFuncSetAttribute((const void*)gemm_bfx<0, false, 1, 2, 0>, cudaFuncAttributeMaxDynamicSharedMemorySize, SMEM_G2);
    cudaFuncSetAttribute((const void*)gemm_bfx<2, true, 3, 2, 1>,  cudaFuncAttributeMaxDynamicSharedMemorySize, SMEM_G5);
    cudaFuncSetAttribute((const void*)gemm_bfx<3, false, 3, 2, 0>, cudaFuncAttributeMaxDynamicSharedMemorySize, SMEM_G6);

    dim3 blk(256);

    // launches 1-3: decompositions (ncu -s targets our launch #4 = G1)
    decomp_split3_kernel<<<MM*DD/2/256, blk>>>((const float2*)x, xh, xm, xl, MM*DD/2);
    decomp_split3_kernel<<<HH*DD/2/256, blk>>>((const float2*)gate_w1, w1h, w1m, w1l, HH*DD/2);
    decomp_hi_kernel<<<(int)((size_t)HH*HH/2/256), blk>>>((const float2*)gate_w2, w2h, (int)((size_t)HH*HH/2));

    // 4 (ncu target): g = relu(x @ w1^T + b1) — bf16x6, 64-row CTAs, 2 CTA/SM
    gemm_bfx<1, false, 6, 2, 2><<<dim3(HH/128, MM/64), blk, SMEM_G1>>>(
        xh, xm, xl, w1h, w1m, w1l, nullptr, nullptr,
        gate_b1, nullptr, gp, ghp, nullptr, HH, DD, DD, 0);

    // 5: scores = g @ w2^T + b2 — bf16-1, 64-row CTAs, 3 CTA/SM
    gemm_bfx<0, false, 1, 2, 0><<<dim3(HH/128, MM/64), blk, SMEM_G2>>>(
        ghp, nullptr, nullptr, w2h, nullptr, nullptr, nullptr, nullptr,
        gate_b2, nullptr, sp, nullptr, nullptr, HH, HH, HH, 0);

    // selection machinery (4 radix passes -> exact bf16-score threshold)
    init_hist<<<8, 256>>>();
    init_misc<<<1, 32>>>();
    init_sel<<<BB * HH / 4 / 256, blk>>>();
    for (int pass = 0; pass < 4; pass++) {
        hist_pass<<<dim3(128, BB), blk>>>(pass);
        scan_pass<<<1, 256>>>();
    }
    thr_kernel<<<1, 32>>>();
    band_kernel<<<dim3(SS*HH/4/256, BB), blk>>>();
    refine_kernel<<<dim3(64, BB), blk>>>(gate_w2, gate_b2);
    select_kernel<<<BB, 256>>>();

    // decompositions for the up/down path (2-plane)
    decomp_split_kernel<<<HH*DD/2/256, blk>>>((const float2*)up_prev_w, uph, upl, HH*DD/2);
    decomp_split_kernel<<<HH*DD/2/256, blk>>>((const float2*)up_curr_w, uch, ucl, HH*DD/2);
    decomp_split_kernel<<<DD*HH/2/256, blk>>>((const float2*)down_w, dwh, dwl, DD*HH/2);

    // h = gelu(x @ mod_w^T + mod_b) — bf16x3, 64-row CTAs (x planes: xh + xm)
    gemm_bfx<2, true, 3, 2, 1><<<dim3(HH/128, MM/64), blk, SMEM_G5>>>(
        xh, xm, nullptr, uph, upl, nullptr, uch, ucl,
        up_prev_b, up_curr_b, nullptr, hhp, hlp, HH, DD, DD, 0);

    // out = h @ down_w^T + down_b — bf16x3, split-K=2 into score_buf scratch
    gemm_bfx<3, false, 3, 2, 0><<<dim3(DD/128, MM/64, 2), blk, SMEM_G6>>>(
        hhp, hlp, nullptr, dwh, dwl, nullptr, nullptr, nullptr,
        nullptr, nullptr, sp, nullptr, nullptr, DD, HH, HH/2, (size_t)MM*DD);
    combine_kernel<<<MM*DD/4/256, blk>>>(
        (const float4*)sp, (const float4*)(sp + (size_t)MM*DD), down_b,
        (float4*)out, MM*DD/4);
}

// round 16
// speedup vs baseline: 1.0472x; 1.0472x over previous
#include <cuda_runtime.h>
#include <math.h>
#include <stdint.h>

// Problem constants
#define BB   8
#define SS   128
#define DD   1024
#define HH   4096
#define MM   (BB*SS)          // 1024
#define KSEL (256*128)        // 32768 = TOPK*S
#define AMB_CAP 32768

// ---------------- scratch (device globals; no allocation) ----------------
__device__ float g_buf[MM*HH];        // fp32 gate hidden (refine ground truth)
__device__ float score_buf[MM*HH];    // scores; reused as split-K scratch later
// packed bf16 plane buffers: [rows][K/2] u32 words
__device__ uint32_t w2h_buf[(size_t)HH*HH/2];
__device__ uint32_t xh_buf[MM*DD/2],  xm_buf[MM*DD/2],  xl_buf[MM*DD/2];
__device__ uint32_t w1h_buf[HH*DD/2], w1m_buf[HH*DD/2], w1l_buf[HH*DD/2];
__device__ uint32_t uph_buf[HH*DD/2], upl_buf[HH*DD/2];
__device__ uint32_t uch_buf[HH*DD/2], ucl_buf[HH*DD/2];
__device__ uint32_t dwh_buf[DD*HH/2], dwl_buf[DD*HH/2];
__device__ uint32_t gh_buf[MM*HH/2];
__device__ uint32_t hh_buf[MM*HH/2],  hl_buf[MM*HH/2];

__device__ unsigned int hist_buf[BB][256];
__device__ unsigned int prefix_buf[BB];
__device__ unsigned int remain_buf[BB];
__device__ float thr_buf[BB];
__device__ int   cin_buf[BB];
__device__ int   ambcnt_buf[BB];
__device__ int   take_buf[BB];
__device__ unsigned int amb_idx[BB][AMB_CAP];
__device__ float amb_val[BB][AMB_CAP];
__device__ unsigned char sel_buf[BB*HH];

// ---------------- small helpers ----------------
__device__ __forceinline__ unsigned int fkey(float f) {
    unsigned int u = __float_as_uint(f);
    return u ^ ((u >> 31) ? 0xFFFFFFFFu : 0x80000000u);
}
__device__ __forceinline__ float key2f(unsigned int k) {
    unsigned int u = (k & 0x80000000u) ? (k ^ 0x80000000u) : ~k;
    return __uint_as_float(u);
}
__device__ __forceinline__ uint32_t smem_u32(const void* p) {
    uint32_t a;
    asm("{ .reg .u64 t; cvta.to.shared.u64 t, %1; cvt.u32.u64 %0, t; }" : "=r"(a) : "l"(p));
    return a;
}
__device__ __forceinline__ void cpasync16(uint32_t saddr, const void* g) {
    asm volatile("cp.async.cg.shared.global [%0], [%1], 16;" :: "r"(saddr), "l"(g));
}
__device__ __forceinline__ void ldmx4(uint32_t& r0, uint32_t& r1, uint32_t& r2,
                                      uint32_t& r3, uint32_t addr) {
    asm volatile("ldmatrix.sync.aligned.m8n8.x4.shared.b16 {%0,%1,%2,%3}, [%4];"
                 : "=r"(r0), "=r"(r1), "=r"(r2), "=r"(r3) : "r"(addr));
}
__device__ __forceinline__ void mma16bf(float* d, const uint32_t* a, const uint32_t* b) {
    asm volatile(
        "mma.sync.aligned.m16n8k16.row.col.f32.bf16.bf16.f32 "
        "{%0,%1,%2,%3}, {%4,%5,%6,%7}, {%8,%9}, {%0,%1,%2,%3};"
        : "+f"(d[0]), "+f"(d[1]), "+f"(d[2]), "+f"(d[3])
        : "r"(a[0]), "r"(a[1]), "r"(a[2]), "r"(a[3]), "r"(b[0]), "r"(b[1]));
}
__device__ __forceinline__ uint32_t pack_bf16(float v0, float v1) {
    uint32_t h;
    asm("cvt.rn.bf16x2.f32 %0, %1, %2;" : "=r"(h) : "f"(v1), "f"(v0));
    return h;
}
__device__ __forceinline__ void unpack_bf16pair(uint32_t w, float& f0, float& f1) {
    f0 = __uint_as_float(w << 16);
    f1 = __uint_as_float(w & 0xFFFF0000u);
}
__device__ __forceinline__ void pack_split_bf16(float v0, float v1,
                                                uint32_t& hi, uint32_t& lo) {
    hi = pack_bf16(v0, v1);
    float h0, h1;
    unpack_bf16pair(hi, h0, h1);
    lo = pack_bf16(v0 - h0, v1 - h1);
}
__device__ __forceinline__ void pack_split3_bf16(float v0, float v1,
                                                 uint32_t& hi, uint32_t& mi, uint32_t& lo) {
    hi = pack_bf16(v0, v1);
    float h0, h1;
    unpack_bf16pair(hi, h0, h1);
    float r0 = v0 - h0, r1 = v1 - h1;
    mi = pack_bf16(r0, r1);
    float m0, m1;
    unpack_bf16pair(mi, m0, m1);
    lo = pack_bf16(r0 - m0, r1 - m1);
}
// EPI: 0 +bias; 1 relu(+bias); 2 select-bias+GELU; 3 raw (split-K partial)
template<int EPI>
__device__ __forceinline__ float epi_apply(float x, int cc, bool se,
                                           const float* bias_p, const float* bias_c) {
    if (EPI == 0) {
        x += bias_p[cc];
    } else if (EPI == 1) {
        x += bias_p[cc];
        x = fmaxf(x, 0.0f);
    } else if (EPI == 2) {
        x += se ? bias_p[cc] : bias_c[cc];
        x = 0.5f * x * (1.0f + erff(x * 0.70710678118654752f));
    }
    return x;
}

// ---------------- decomposition kernels ----------------
__global__ void decomp_split3_kernel(const float2* __restrict__ src,
                                     uint32_t* __restrict__ h, uint32_t* __restrict__ m,
                                     uint32_t* __restrict__ l, int n2) {
    int i = blockIdx.x * blockDim.x + threadIdx.x;
    if (i >= n2) return;
    float2 v = src[i];
    uint32_t hh, mm, ll;
    pack_split3_bf16(v.x, v.y, hh, mm, ll);
    h[i] = hh; m[i] = mm; l[i] = ll;
}
__global__ void decomp_split_kernel(const float2* __restrict__ src,
                                    uint32_t* __restrict__ hi,
                                    uint32_t* __restrict__ lo, int n2) {
    int i = blockIdx.x * blockDim.x + threadIdx.x;
    if (i >= n2) return;
    float2 v = src[i];
    uint32_t h, l;
    pack_split_bf16(v.x, v.y, h, l);
    hi[i] = h; lo[i] = l;
}
__global__ void decomp_hi_kernel(const float2* __restrict__ src,
                                 uint32_t* __restrict__ hi, int n2) {
    int i = blockIdx.x * blockDim.x + threadIdx.x;
    if (i >= n2) return;
    float2 v = src[i];
    hi[i] = pack_bf16(v.x, v.y);
}

// ---------------- split-K combine: out = p0 + p1 + bias ----------------
__global__ void combine_kernel(const float4* __restrict__ p0,
                               const float4* __restrict__ p1,
                               const float* __restrict__ bias,
                               float4* __restrict__ out, int n4) {
    int i = blockIdx.x * blockDim.x + threadIdx.x;
    if (i >= n4) return;
    float4 a = p0[i], b = p1[i];
    const float4 bb = *(const float4*)(bias + ((i * 4) & (DD - 1)));
    a.x += b.x + bb.x; a.y += b.y + bb.y;
    a.z += b.z + bb.z; a.w += b.w + bb.w;
    out[i] = a;
}

// ---------------- init ----------------
__global__ void init_hist() {
    int t = blockIdx.x * blockDim.x + threadIdx.x;
    if (t < BB * 256) ((unsigned int*)hist_buf)[t] = 0u;
}
__global__ void init_misc() {
    int t = threadIdx.x;
    if (t < BB) {
        prefix_buf[t] = 0u; remain_buf[t] = KSEL;
        cin_buf[t] = 0; ambcnt_buf[t] = 0; take_buf[t] = 0;
    }
}
__global__ void init_sel() {
    int t = blockIdx.x * blockDim.x + threadIdx.x;
    ((unsigned int*)sel_buf)[t] = 0u;
}

// ---------------- radix select (4 passes -> exact 32-bit threshold) --------
__global__ void __launch_bounds__(256) hist_pass(int pass) {
    __shared__ unsigned int sh[256];
    int b = blockIdx.y;
    for (int i = threadIdx.x; i < 256; i += blockDim.x) sh[i] = 0;
    __syncthreads();
    unsigned int pre = prefix_buf[b];
    int shift = 24 - 8 * pass;
    const float4* sb = (const float4*)(score_buf + (size_t)b * SS * HH);
    int total = SS * HH / 4;
    for (int i = blockIdx.x * blockDim.x + threadIdx.x; i < total;
         i += gridDim.x * blockDim.x) {
        float4 v = sb[i];
        unsigned int k0 = fkey(v.x), k1 = fkey(v.y), k2 = fkey(v.z), k3 = fkey(v.w);
        if (pass == 0) {
            atomicAdd(&sh[(k0 >> shift) & 0xFF], 1u);
            atomicAdd(&sh[(k1 >> shift) & 0xFF], 1u);
            atomicAdd(&sh[(k2 >> shift) & 0xFF], 1u);
            atomicAdd(&sh[(k3 >> shift) & 0xFF], 1u);
        } else {
            if ((k0 >> (shift + 8)) == pre) atomicAdd(&sh[(k0 >> shift) & 0xFF], 1u);
            if ((k1 >> (shift + 8)) == pre) atomicAdd(&sh[(k1 >> shift) & 0xFF], 1u);
            if ((k2 >> (shift + 8)) == pre) atomicAdd(&sh[(k2 >> shift) & 0xFF], 1u);
            if ((k3 >> (shift + 8)) == pre) atomicAdd(&sh[(k3 >> shift) & 0xFF], 1u);
        }
    }
    __syncthreads();
    for (int i = threadIdx.x; i < 256; i += blockDim.x)
        if (sh[i]) atomicAdd(&hist_buf[b][i], sh[i]);
}

__global__ void scan_pass() {
    int t = threadIdx.x;
    if (t < BB) {
        unsigned int r = remain_buf[t];
        unsigned int cum = 0;
        for (int bin = 255; bin >= 0; bin--) {
            unsigned int c = hist_buf[t][bin];
            if (cum + c >= r) {
                prefix_buf[t] = (prefix_buf[t] << 8) | (unsigned int)bin;
                remain_buf[t] = r - cum;
                break;
            }
            cum += c;
        }
    }
    __syncthreads();
    for (int i = threadIdx.x; i < BB * 256; i += blockDim.x)
        ((unsigned int*)hist_buf)[i] = 0u;
}

__global__ void thr_kernel() {
    int t = threadIdx.x;
    if (t < BB) thr_buf[t] = key2f(prefix_buf[t]);   // exact bf16-score kth value
}

// ---------------- band + refine + select ----------------
__global__ void __launch_bounds__(256) band_kernel() {
    int b = blockIdx.y;
    float T = thr_buf[b];
    float del = fmaxf(1e-2f, 1e-2f * fabsf(T));
    float Thi = T + del, Tlo = T - del;
    __shared__ int scnt;
    if (threadIdx.x == 0) scnt = 0;
    __syncthreads();
    int i = blockIdx.x * blockDim.x + threadIdx.x;
    const float4* sb = (const float4*)(score_buf + (size_t)b * SS * HH);
    float4 v = sb[i];
    float f[4] = { v.x, v.y, v.z, v.w };
    int base = i * 4;
    #pragma unroll
    for (int q = 0; q < 4; q++) {
        if (f[q] > Thi) {
            atomicAdd(&scnt, 1);
            sel_buf[b * HH + ((base + q) & (HH - 1))] = 1;
        } else if (f[q] > Tlo) {
            int p = atomicAdd(&ambcnt_buf[b], 1);
            if (p < AMB_CAP) amb_idx[b][p] = (unsigned int)(base + q);
        }
    }
    __syncthreads();
    if (threadIdx.x == 0 && scnt) atomicAdd(&cin_buf[b], scnt);
}

__global__ void __launch_bounds__(256) refine_kernel(const float* __restrict__ w2,
                                                     const float* __restrict__ b2) {
    int b = blockIdx.y;
    int n = min(ambcnt_buf[b], AMB_CAP);
    int wid = (blockIdx.x * blockDim.x + threadIdx.x) >> 5;
    int lid = threadIdx.x & 31;
    int nwarps = (gridDim.x * blockDim.x) >> 5;
    for (int it = wid; it < n; it += nwarps) {
        unsigned int idx = amb_idx[b][it];
        int h = idx & (HH - 1);
        const float* grow = g_buf + (size_t)b * SS * HH + (idx - h);
        const float* wrow = w2 + (size_t)h * HH;
        float s = 0.0f;
        for (int j = lid * 4; j < HH; j += 128) {
            float4 gg = *(const float4*)(grow + j);
            float4 ww = *(const float4*)(wrow + j);
            s += gg.x * ww.x + gg.y * ww.y + gg.z * ww.z + gg.w * ww.w;
        }
        #pragma unroll
        for (int o = 16; o > 0; o >>= 1)
            s += __shfl_xor_sync(0xFFFFFFFFu, s, o);
        if (lid == 0) amb_val[b][it] = s + b2[h];
    }
}

__global__ void __launch_bounds__(256) select_kernel() {
    int b = blockIdx.x;
    int n = min(ambcnt_buf[b], AMB_CAP);
    int slots = KSEL - cin_buf[b];
    if (slots < 0) slots = 0;
    if (slots > n) slots = n;
    __shared__ int red[256];

    unsigned int lo = 0u, hi = 0xFFFFFFFFu;
    while (lo < hi) {
        unsigned int mid = lo + ((hi - lo) >> 1) + 1u;
        int c = 0;
        for (int i = threadIdx.x; i < n; i += 256)
            c += (fkey(amb_val[b][i]) >= mid) ? 1 : 0;
        red[threadIdx.x] = c;
        __syncthreads();
        for (int o = 128; o > 0; o >>= 1) {
            if (threadIdx.x < o) red[threadIdx.x] += red[threadIdx.x + o];
            __syncthreads();
        }
        if (red[0] >= slots) lo = mid; else hi = mid - 1u;
        __syncthreads();
    }
    const unsigned int Kstar = lo;
    int c = 0;
    for (int i = threadIdx.x; i < n; i += 256)
        c += (fkey(amb_val[b][i]) > Kstar) ? 1 : 0;
    red[threadIdx.x] = c;
    __syncthreads();
    for (int o = 128; o > 0; o >>= 1) {
        if (threadIdx.x < o) red[threadIdx.x] += red[threadIdx.x + o];
        __syncthreads();
    }
    const int need = slots - red[0];
    for (int i = threadIdx.x; i < n; i += 256) {
        unsigned int k = fkey(amb_val[b][i]);
        bool m = false;
        if (k > Kstar) m = true;
        else if (k == Kstar) {
            int p = atomicAdd(&take_buf[b], 1);
            if (p < need) m = true;
        }
        if (m) sel_buf[b * HH + (amb_idx[b][i] & (HH - 1))] = 1;
    }
}

// ---------------- bf16 NT GEMM: cp.async (2-stage, R9 loop) + ldmatrix ------
// A,B pre-packed bf16 planes in GMEM as [rows][K/2] u32 words.
// NT: 1 / 3 / 6 -> plane count PA = 1 / 2 / 3; MMA set: (i,j) with i+j < PA.
// MT: m-subtiles per warp (4 -> 128-row CTA, 2 -> 64-row CTA).
// OUT: 0 = fp32 C; 1 = packed bf16 hi/lo; 2 = fp32 C + bf16 hi.
// SPLITZ: compile-time split-K factor. SPLITZ==1 compiles exactly like R14.
#define LDBW 20   // u32 words per SMEM row (80B stride)

template<int EPI, bool SELB, int NT, int MT, int OUT, int SPLITZ>
__global__ void __launch_bounds__(256, (NT == 1 || MT == 2) ? 2 : 1)
gemm_bfx(const uint32_t* __restrict__ A0, const uint32_t* __restrict__ A1,
         const uint32_t* __restrict__ A2,
         const uint32_t* __restrict__ B0p, const uint32_t* __restrict__ B1p,
         const uint32_t* __restrict__ B2p,
         const uint32_t* __restrict__ B0c, const uint32_t* __restrict__ B1c,
         const float* __restrict__ bias_p, const float* __restrict__ bias_c,
         float* __restrict__ Cf, uint32_t* __restrict__ Ch, uint32_t* __restrict__ Cl,
         int N, int K)
{
    constexpr int PA = (NT == 1) ? 1 : (NT == 3) ? 2 : 3;
    constexpr int CTA_ROWS = MT * 32;
    constexpr int A_TILE_U = CTA_ROWS * LDBW;
    constexpr int B_TILE_U = 128 * LDBW;
    constexpr int STAGE_U  = PA * (A_TILE_U + B_TILE_U);
    constexpr int AUPT     = (CTA_ROWS * 4) / 256;

    extern __shared__ uint32_t smu[];
    const uint32_t sbase = smem_u32(smu);

    const int tid = threadIdx.x;
    const int wid = tid >> 5;
    const int lid = tid & 31;
    const int g   = lid >> 2;
    const int cth = lid & 3;
    const int wm  = wid & 1;
    const int wn  = wid >> 1;
    const int mBase = blockIdx.y * CTA_ROWS;
    const int nBase = blockIdx.x * 128;
    const int KW = K >> 1;

    // split-K (compile-time): z-slice offset into K and partial output buffer
    int koffw;
    float* Cfp;
    if constexpr (SPLITZ > 1) {
        koffw = blockIdx.z * (K / SPLITZ / 2);
        Cfp = Cf + (size_t)blockIdx.z * ((size_t)MM * DD);
    } else {
        koffw = 0;
        Cfp = Cf;
    }

    const uint32_t* Ag[3] = { A0, A1, A2 };
    const uint32_t* Bg[3] = { B0p, B1p, B2p };

    // batch = row block / SS (CTA rows never straddle a batch: 64 | 128)
    const unsigned char* selrow = SELB ? (sel_buf + (size_t)(mBase >> 7) * HH)
                                       : (const unsigned char*)0;

    float acc[MT][4][4];
    #pragma unroll
    for (int a = 0; a < MT; a++)
        #pragma unroll
        for (int b = 0; b < 4; b++)
            #pragma unroll
            for (int q = 0; q < 4; q++) acc[a][b][q] = 0.0f;

    const int nslab = (K / SPLITZ) >> 5;

    auto issue = [&](int s) {
        const int stg = s & 1;
        const int kw = koffw + s * 16;
        const uint32_t st = sbase + (uint32_t)stg * (STAGE_U * 4);
        #pragma unroll
        for (int t = 0; t < AUPT; t++) {
            const int u = t * 256 + tid;
            const int row = u >> 2, ch = u & 3;
            const uint32_t so = (uint32_t)(row * LDBW + ch * 4) * 4;
            const size_t go = (size_t)(mBase + row) * KW + kw + ch * 4;
            #pragma unroll
            for (int p = 0; p < PA; p++)
                cpasync16(st + (uint32_t)p * (A_TILE_U * 4) + so, Ag[p] + go);
        }
        #pragma unroll
        for (int t = 0; t < 2; t++) {
            const int u = t * 256 + tid;
            const int row = u >> 2, ch = u & 3;
            const int nrow = nBase + row;
            const uint32_t so = (uint32_t)(row * LDBW + ch * 4) * 4;
            const size_t go = (size_t)nrow * KW + kw + ch * 4;
            const uint32_t bb = st + (uint32_t)(PA * A_TILE_U) * 4;
            if (SELB) {
                const bool se = selrow[nrow] != 0;
                cpasync16(bb + so, (se ? B0p : B0c) + go);
                if (PA >= 2)
                    cpasync16(bb + (uint32_t)(B_TILE_U * 4) + so, (se ? B1p : B1c) + go);
            } else {
                #pragma unroll
                for (int p = 0; p < PA; p++)
                    cpasync16(bb + (uint32_t)p * (B_TILE_U * 4) + so, Bg[p] + go);
            }
        }
        asm volatile("cp.async.commit_group;" ::: "memory");
    };

    auto compute = [&](int stg) {
        const uint32_t st = sbase + (uint32_t)stg * (STAGE_U * 4);
        #pragma unroll
        for (int ks = 0; ks < 2; ks++) {
            const int pc0 = ks * 8;
            uint32_t bfr[PA][4][2];
            #pragma unroll
            for (int p = 0; p < PA; p++) {
                const uint32_t BS = st + (uint32_t)(PA * A_TILE_U + p * B_TILE_U) * 4;
                #pragma unroll
                for (int nip = 0; nip < 2; nip++) {
                    const int nb2 = wn * 32 + nip * 16;
                    const uint32_t ba = (uint32_t)((nb2 + (lid & 7) + ((lid >> 4) & 1) * 8)
                                        * LDBW + pc0) * 4 + ((lid >> 3) & 1) * 16;
                    ldmx4(bfr[p][2*nip][0], bfr[p][2*nip][1],
                          bfr[p][2*nip+1][0], bfr[p][2*nip+1][1], BS + ba);
                }
            }
            #pragma unroll
            for (int mi = 0; mi < MT; mi++) {
                const int rb = wm * (MT * 16) + mi * 16;
                const uint32_t aoff = (uint32_t)((rb + (lid & 15)) * LDBW + pc0) * 4
                                      + (lid >> 4) * 16;
                uint32_t afr[PA][4];
                #pragma unroll
                for (int p = 0; p < PA; p++)
                    ldmx4(afr[p][0], afr[p][1], afr[p][2], afr[p][3],
                          st + (uint32_t)p * (A_TILE_U * 4) + aoff);
                #pragma unroll
                for (int ni = 0; ni < 4; ni++) {
                    #pragma unroll
                    for (int o = PA - 1; o >= 0; o--)      // o = i + j
                        #pragma unroll
                        for (int i = 0; i <= o; i++)
                            mma16bf(acc[mi][ni], afr[i], bfr[o - i][ni]);
                }
            }
        }
    };

    // R9 proven loop: issue-before-wait, 2 stages, 2 syncs
    issue(0);
    for (int s = 0; s < nslab; s++) {
        if (s + 1 < nslab) {
            issue(s + 1);
            asm volatile("cp.async.wait_group 1;" ::: "memory");
        } else {
            asm volatile("cp.async.wait_group 0;" ::: "memory");
        }
        __syncthreads();
        compute(s & 1);
        __syncthreads();
    }

    #pragma unroll
    for (int mi = 0; mi < MT; mi++) {
        const int r0 = mBase + wm * (MT * 16) + mi * 16 + g;
        #pragma unroll
        for (int ni = 0; ni < 4; ni++) {
            const int col = nBase + wn * 32 + ni * 8 + 2 * cth;
            float v[4] = { acc[mi][ni][0], acc[mi][ni][1],
                           acc[mi][ni][2], acc[mi][ni][3] };
            #pragma unroll
            for (int q = 0; q < 4; q++) {
                const int cc = col + (q & 1);
                const bool se = SELB ? (selrow[cc] != 0) : false;
                v[q] = epi_apply<EPI>(v[q], cc, se, bias_p, bias_c);
            }
            if (OUT == 0 || OUT == 2) {
                *(float2*)(Cfp + (size_t)r0 * N + col)       = make_float2(v[0], v[1]);
                *(float2*)(Cfp + (size_t)(r0 + 8) * N + col) = make_float2(v[2], v[3]);
            }
            if (OUT == 1) {
                uint32_t h, l;
                pack_split_bf16(v[0], v[1], h, l);
                Ch[((size_t)r0 * N + col) >> 1] = h;
                Cl[((size_t)r0 * N + col) >> 1] = l;
                pack_split_bf16(v[2], v[3], h, l);
                Ch[((size_t)(r0 + 8) * N + col) >> 1] = h;
                Cl[((size_t)(r0 + 8) * N + col) >> 1] = l;
            }
            if (OUT == 2) {
                Ch[((size_t)r0 * N + col) >> 1]       = pack_bf16(v[0], v[1]);
                Ch[((size_t)(r0 + 8) * N + col) >> 1] = pack_bf16(v[2], v[3]);
            }
        }
    }
}

// SMEM sizes (bytes, 2 stages)
#define SMEM_G1 (2 * 3 * ((64*LDBW) + (128*LDBW)) * 4)      // NT=6, MT=2: 92KB -> 2 CTA/SM
#define SMEM_G2 (2 * 1 * ((128*LDBW) + (128*LDBW)) * 4)     // NT=1, MT=4: 40KB -> 2 CTA/SM
#define SMEM_G5 (2 * 2 * ((64*LDBW)  + (128*LDBW)) * 4)     // NT=3, MT=2: 60KB -> 2 CTA/SM
#define SMEM_G6 (2 * 2 * ((64*LDBW)  + (128*LDBW)) * 4)     // NT=3, MT=2: 60KB -> 2 CTA/SM

// ---------------- launch ----------------
extern "C" void kernel_launch(void* const* d_in, const int* in_sizes, int n_in,
                              void* d_out, int out_size)
{
    const float* x         = (const float*)d_in[0];   // [B,S,D]
    const float* up_prev_w = (const float*)d_in[1];   // [H,D]
    const float* up_prev_b = (const float*)d_in[2];   // [H]
    const float* up_curr_w = (const float*)d_in[3];   // [H,D]
    const float* up_curr_b = (const float*)d_in[4];   // [H]
    const float* gate_w1   = (const float*)d_in[5];   // [H,D]
    const float* gate_b1   = (const float*)d_in[6];   // [H]
    const float* gate_w2   = (const float*)d_in[7];   // [H,H]
    const float* gate_b2   = (const float*)d_in[8];   // [H]
    const float* down_w    = (const float*)d_in[9];   // [D,H]
    const float* down_b    = (const float*)d_in[10];  // [D]
    float* out = (float*)d_out;                       // [B,S,D]

    float *gp, *sp;
    uint32_t *w2h, *xh, *xm, *xl, *w1h, *w1m, *w1l;
    uint32_t *uph, *upl, *uch, *ucl, *dwh, *dwl, *ghp, *hhp, *hlp;
    cudaGetSymbolAddress((void**)&gp,  g_buf);
    cudaGetSymbolAddress((void**)&sp,  score_buf);
    cudaGetSymbolAddress((void**)&w2h, w2h_buf);
    cudaGetSymbolAddress((void**)&xh,  xh_buf);
    cudaGetSymbolAddress((void**)&xm,  xm_buf);
    cudaGetSymbolAddress((void**)&xl,  xl_buf);
    cudaGetSymbolAddress((void**)&w1h, w1h_buf);
    cudaGetSymbolAddress((void**)&w1m, w1m_buf);
    cudaGetSymbolAddress((void**)&w1l, w1l_buf);
    cudaGetSymbolAddress((void**)&uph, uph_buf);  cudaGetSymbolAddress((void**)&upl, upl_buf);
    cudaGetSymbolAddress((void**)&uch, uch_buf);  cudaGetSymbolAddress((void**)&ucl, ucl_buf);
    cudaGetSymbolAddress((void**)&dwh, dwh_buf);  cudaGetSymbolAddress((void**)&dwl, dwl_buf);
    cudaGetSymbolAddress((void**)&ghp, gh_buf);
    cudaGetSymbolAddress((void**)&hhp, hh_buf);   cudaGetSymbolAddress((void**)&hlp, hl_buf);

    cudaFuncSetAttribute((const void*)gemm_bfx<1, false, 6, 2, 2, 1>, cudaFuncAttributeMaxDynamicSharedMemorySize, SMEM_G1);
    cudaFuncSetAttribute((const void*)gemm_bfx<0, false, 1, 4, 0, 1>, cudaFuncAttributeMaxDynamicSharedMemorySize, SMEM_G2);
    cudaFuncSetAttribute((const void*)gemm_bfx<2, true, 3, 2, 1, 1>,  cudaFuncAttributeMaxDynamicSharedMemorySize, SMEM_G5);
    cudaFuncSetAttribute((const void*)gemm_bfx<3, false, 3, 2, 0, 2>, cudaFuncAttributeMaxDynamicSharedMemorySize, SMEM_G6);

    dim3 blk(256);

    // launches 1-3: decompositions (ncu -s targets our launch #4 = G1)
    decomp_split3_kernel<<<MM*DD/2/256, blk>>>((const float2*)x, xh, xm, xl, MM*DD/2);
    decomp_split3_kernel<<<HH*DD/2/256, blk>>>((const float2*)gate_w1, w1h, w1m, w1l, HH*DD/2);
    decomp_hi_kernel<<<(int)((size_t)HH*HH/2/256), blk>>>((const float2*)gate_w2, w2h, (int)((size_t)HH*HH/2));

    // 4 (ncu target): g = relu(x @ w1^T + b1) — bf16x6, 64-row CTAs, 2 CTA/SM
    gemm_bfx<1, false, 6, 2, 2, 1><<<dim3(HH/128, MM/64), blk, SMEM_G1>>>(
        xh, xm, xl, w1h, w1m, w1l, nullptr, nullptr,
        gate_b1, nullptr, gp, ghp, nullptr, HH, DD);

    // 5: scores = g @ w2^T + b2 — bf16-1 (R14 config: MT=4, 2 CTA/SM)
    gemm_bfx<0, false, 1, 4, 0, 1><<<dim3(HH/128, MM/128), blk, SMEM_G2>>>(
        ghp, nullptr, nullptr, w2h, nullptr, nullptr, nullptr, nullptr,
        gate_b2, nullptr, sp, nullptr, nullptr, HH, HH);

    // selection machinery (4 radix passes -> exact bf16-score threshold)
    init_hist<<<8, 256>>>();
    init_misc<<<1, 32>>>();
    init_sel<<<BB * HH / 4 / 256, blk>>>();
    for (int pass = 0; pass < 4; pass++) {
        hist_pass<<<dim3(128, BB), blk>>>(pass);
        scan_pass<<<1, 256>>>();
    }
    thr_kernel<<<1, 32>>>();
    band_kernel<<<dim3(SS*HH/4/256, BB), blk>>>();
    refine_kernel<<<dim3(64, BB), blk>>>(gate_w2, gate_b2);
    select_kernel<<<BB, 256>>>();

    // decompositions for the up/down path (2-plane)
    decomp_split_kernel<<<HH*DD/2/256, blk>>>((const float2*)up_prev_w, uph, upl, HH*DD/2);
    decomp_split_kernel<<<HH*DD/2/256, blk>>>((const float2*)up_curr_w, uch, ucl, HH*DD/2);
    decomp_split_kernel<<<DD*HH/2/256, blk>>>((const float2*)down_w, dwh, dwl, DD*HH/2);

    // h = gelu(x @ mod_w^T + mod_b) — bf16x3, 64-row CTAs (x planes: xh + xm)
    gemm_bfx<2, true, 3, 2, 1, 1><<<dim3(HH/128, MM/64), blk, SMEM_G5>>>(
        xh, xm, nullptr, uph, upl, nullptr, uch, ucl,
        up_prev_b, up_curr_b, nullptr, hhp, hlp, HH, DD);

    // out = h @ down_w^T + down_b — bf16x3, split-K=2 into score_buf scratch
    gemm_bfx<3, false, 3, 2, 0, 2><<<dim3(DD/128, MM/64, 2), blk, SMEM_G6>>>(
        hhp, hlp, nullptr, dwh, dwl, nullptr, nullptr, nullptr,
        nullptr, nullptr, sp, nullptr, nullptr, DD, HH);
    combine_kernel<<<MM*DD/4/256, blk>>>(
        (const float4*)sp, (const float4*)(sp + (size_t)MM*DD), down_b,
        (float4*)out, MM*DD/4);
}

// round 17
// speedup vs baseline: 1.1203x; 1.0698x over previous
#include <cuda_runtime.h>
#include <math.h>
#include <stdint.h>

// Problem constants
#define BB   8
#define SS   128
#define DD   1024
#define HH   4096
#define MM   (BB*SS)          // 1024
#define KSEL (256*128)        // 32768 = TOPK*S
#define AMB_CAP 32768

// ---------------- scratch (device globals; no allocation) ----------------
__device__ float g_buf[MM*HH];        // fp32 gate hidden (refine ground truth)
__device__ float score_buf[MM*HH];    // scores; reused as split-K scratch later
// packed bf16 plane buffers: [rows][K/2] u32 words
__device__ uint32_t w2h_buf[(size_t)HH*HH/2];
__device__ uint32_t xh_buf[MM*DD/2],  xm_buf[MM*DD/2],  xl_buf[MM*DD/2];
__device__ uint32_t w1h_buf[HH*DD/2], w1m_buf[HH*DD/2], w1l_buf[HH*DD/2];
__device__ uint32_t uph_buf[HH*DD/2], upl_buf[HH*DD/2];
__device__ uint32_t uch_buf[HH*DD/2], ucl_buf[HH*DD/2];
__device__ uint32_t dwh_buf[DD*HH/2], dwl_buf[DD*HH/2];
__device__ uint32_t gh_buf[MM*HH/2];
__device__ uint32_t hh_buf[MM*HH/2],  hl_buf[MM*HH/2];

__device__ unsigned int hist_buf[BB][256];
__device__ unsigned int prefix_buf[BB];
__device__ unsigned int remain_buf[BB];
__device__ float thr_buf[BB];
__device__ int   cin_buf[BB];
__device__ int   ambcnt_buf[BB];
__device__ int   take_buf[BB];
__device__ unsigned int amb_idx[BB][AMB_CAP];
__device__ float amb_val[BB][AMB_CAP];
__device__ unsigned char sel_buf[BB*HH];

// ---------------- small helpers ----------------
__device__ __forceinline__ unsigned int fkey(float f) {
    unsigned int u = __float_as_uint(f);
    return u ^ ((u >> 31) ? 0xFFFFFFFFu : 0x80000000u);
}
__device__ __forceinline__ float key2f(unsigned int k) {
    unsigned int u = (k & 0x80000000u) ? (k ^ 0x80000000u) : ~k;
    return __uint_as_float(u);
}
__device__ __forceinline__ uint32_t smem_u32(const void* p) {
    uint32_t a;
    asm("{ .reg .u64 t; cvta.to.shared.u64 t, %1; cvt.u32.u64 %0, t; }" : "=r"(a) : "l"(p));
    return a;
}
__device__ __forceinline__ void cpasync16(uint32_t saddr, const void* g) {
    asm volatile("cp.async.cg.shared.global [%0], [%1], 16;" :: "r"(saddr), "l"(g));
}
__device__ __forceinline__ void ldmx4(uint32_t& r0, uint32_t& r1, uint32_t& r2,
                                      uint32_t& r3, uint32_t addr) {
    asm volatile("ldmatrix.sync.aligned.m8n8.x4.shared.b16 {%0,%1,%2,%3}, [%4];"
                 : "=r"(r0), "=r"(r1), "=r"(r2), "=r"(r3) : "r"(addr));
}
__device__ __forceinline__ void mma16bf(float* d, const uint32_t* a, const uint32_t* b) {
    asm volatile(
        "mma.sync.aligned.m16n8k16.row.col.f32.bf16.bf16.f32 "
        "{%0,%1,%2,%3}, {%4,%5,%6,%7}, {%8,%9}, {%0,%1,%2,%3};"
        : "+f"(d[0]), "+f"(d[1]), "+f"(d[2]), "+f"(d[3])
        : "r"(a[0]), "r"(a[1]), "r"(a[2]), "r"(a[3]), "r"(b[0]), "r"(b[1]));
}
__device__ __forceinline__ uint32_t pack_bf16(float v0, float v1) {
    uint32_t h;
    asm("cvt.rn.bf16x2.f32 %0, %1, %2;" : "=r"(h) : "f"(v1), "f"(v0));
    return h;
}
__device__ __forceinline__ void unpack_bf16pair(uint32_t w, float& f0, float& f1) {
    f0 = __uint_as_float(w << 16);
    f1 = __uint_as_float(w & 0xFFFF0000u);
}
__device__ __forceinline__ void pack_split_bf16(float v0, float v1,
                                                uint32_t& hi, uint32_t& lo) {
    hi = pack_bf16(v0, v1);
    float h0, h1;
    unpack_bf16pair(hi, h0, h1);
    lo = pack_bf16(v0 - h0, v1 - h1);
}
__device__ __forceinline__ void pack_split3_bf16(float v0, float v1,
                                                 uint32_t& hi, uint32_t& mi, uint32_t& lo) {
    hi = pack_bf16(v0, v1);
    float h0, h1;
    unpack_bf16pair(hi, h0, h1);
    float r0 = v0 - h0, r1 = v1 - h1;
    mi = pack_bf16(r0, r1);
    float m0, m1;
    unpack_bf16pair(mi, m0, m1);
    lo = pack_bf16(r0 - m0, r1 - m1);
}
// EPI: 0 +bias; 1 relu(+bias); 2 select-bias+GELU; 3 raw (split-K partial)
template<int EPI>
__device__ __forceinline__ float epi_apply(float x, int cc, bool se,
                                           const float* bias_p, const float* bias_c) {
    if (EPI == 0) {
        x += bias_p[cc];
    } else if (EPI == 1) {
        x += bias_p[cc];
        x = fmaxf(x, 0.0f);
    } else if (EPI == 2) {
        x += se ? bias_p[cc] : bias_c[cc];
        x = 0.5f * x * (1.0f + erff(x * 0.70710678118654752f));
    }
    return x;
}

// ---------------- decomposition kernels ----------------
__global__ void decomp_split3_kernel(const float2* __restrict__ src,
                                     uint32_t* __restrict__ h, uint32_t* __restrict__ m,
                                     uint32_t* __restrict__ l, int n2) {
    int i = blockIdx.x * blockDim.x + threadIdx.x;
    if (i >= n2) return;
    float2 v = src[i];
    uint32_t hh, mm, ll;
    pack_split3_bf16(v.x, v.y, hh, mm, ll);
    h[i] = hh; m[i] = mm; l[i] = ll;
}
__global__ void decomp_split_kernel(const float2* __restrict__ src,
                                    uint32_t* __restrict__ hi,
                                    uint32_t* __restrict__ lo, int n2) {
    int i = blockIdx.x * blockDim.x + threadIdx.x;
    if (i >= n2) return;
    float2 v = src[i];
    uint32_t h, l;
    pack_split_bf16(v.x, v.y, h, l);
    hi[i] = h; lo[i] = l;
}
__global__ void decomp_hi_kernel(const float2* __restrict__ src,
                                 uint32_t* __restrict__ hi, int n2) {
    int i = blockIdx.x * blockDim.x + threadIdx.x;
    if (i >= n2) return;
    float2 v = src[i];
    hi[i] = pack_bf16(v.x, v.y);
}

// ---------------- split-K combine: out = p0 + p1 + bias ----------------
__global__ void combine_kernel(const float4* __restrict__ p0,
                               const float4* __restrict__ p1,
                               const float* __restrict__ bias,
                               float4* __restrict__ out, int n4) {
    int i = blockIdx.x * blockDim.x + threadIdx.x;
    if (i >= n4) return;
    float4 a = p0[i], b = p1[i];
    const float4 bb = *(const float4*)(bias + ((i * 4) & (DD - 1)));
    a.x += b.x + bb.x; a.y += b.y + bb.y;
    a.z += b.z + bb.z; a.w += b.w + bb.w;
    out[i] = a;
}

// ---------------- init ----------------
__global__ void init_hist() {
    int t = blockIdx.x * blockDim.x + threadIdx.x;
    if (t < BB * 256) ((unsigned int*)hist_buf)[t] = 0u;
}
__global__ void init_misc() {
    int t = threadIdx.x;
    if (t < BB) {
        prefix_buf[t] = 0u; remain_buf[t] = KSEL;
        cin_buf[t] = 0; ambcnt_buf[t] = 0; take_buf[t] = 0;
    }
}
__global__ void init_sel() {
    int t = blockIdx.x * blockDim.x + threadIdx.x;
    ((unsigned int*)sel_buf)[t] = 0u;
}

// ---------------- radix select (4 passes -> exact 32-bit threshold) --------
__global__ void __launch_bounds__(256) hist_pass(int pass) {
    __shared__ unsigned int sh[256];
    int b = blockIdx.y;
    for (int i = threadIdx.x; i < 256; i += blockDim.x) sh[i] = 0;
    __syncthreads();
    unsigned int pre = prefix_buf[b];
    int shift = 24 - 8 * pass;
    const float4* sb = (const float4*)(score_buf + (size_t)b * SS * HH);
    int total = SS * HH / 4;
    for (int i = blockIdx.x * blockDim.x + threadIdx.x; i < total;
         i += gridDim.x * blockDim.x) {
        float4 v = sb[i];
        unsigned int k0 = fkey(v.x), k1 = fkey(v.y), k2 = fkey(v.z), k3 = fkey(v.w);
        if (pass == 0) {
            atomicAdd(&sh[(k0 >> shift) & 0xFF], 1u);
            atomicAdd(&sh[(k1 >> shift) & 0xFF], 1u);
            atomicAdd(&sh[(k2 >> shift) & 0xFF], 1u);
            atomicAdd(&sh[(k3 >> shift) & 0xFF], 1u);
        } else {
            if ((k0 >> (shift + 8)) == pre) atomicAdd(&sh[(k0 >> shift) & 0xFF], 1u);
            if ((k1 >> (shift + 8)) == pre) atomicAdd(&sh[(k1 >> shift) & 0xFF], 1u);
            if ((k2 >> (shift + 8)) == pre) atomicAdd(&sh[(k2 >> shift) & 0xFF], 1u);
            if ((k3 >> (shift + 8)) == pre) atomicAdd(&sh[(k3 >> shift) & 0xFF], 1u);
        }
    }
    __syncthreads();
    for (int i = threadIdx.x; i < 256; i += blockDim.x)
        if (sh[i]) atomicAdd(&hist_buf[b][i], sh[i]);
}

__global__ void scan_pass() {
    int t = threadIdx.x;
    if (t < BB) {
        unsigned int r = remain_buf[t];
        unsigned int cum = 0;
        for (int bin = 255; bin >= 0; bin--) {
            unsigned int c = hist_buf[t][bin];
            if (cum + c >= r) {
                prefix_buf[t] = (prefix_buf[t] << 8) | (unsigned int)bin;
                remain_buf[t] = r - cum;
                break;
            }
            cum += c;
        }
    }
    __syncthreads();
    for (int i = threadIdx.x; i < BB * 256; i += blockDim.x)
        ((unsigned int*)hist_buf)[i] = 0u;
}

__global__ void thr_kernel() {
    int t = threadIdx.x;
    if (t < BB) thr_buf[t] = key2f(prefix_buf[t]);   // exact bf16-score kth value
}

// ---------------- band + refine + select ----------------
// Band: +-3e-3 around the exact bf16-score kth value. bf16-1 score error
// sigma ~= 4e-4 -> 7.5 sigma; expected misclassifications ~ 0.
__global__ void __launch_bounds__(256) band_kernel() {
    int b = blockIdx.y;
    float T = thr_buf[b];
    float del = fmaxf(3e-3f, 3e-3f * fabsf(T));
    float Thi = T + del, Tlo = T - del;
    __shared__ int scnt;
    if (threadIdx.x == 0) scnt = 0;
    __syncthreads();
    int i = blockIdx.x * blockDim.x + threadIdx.x;
    const float4* sb = (const float4*)(score_buf + (size_t)b * SS * HH);
    float4 v = sb[i];
    float f[4] = { v.x, v.y, v.z, v.w };
    int base = i * 4;
    #pragma unroll
    for (int q = 0; q < 4; q++) {
        if (f[q] > Thi) {
            atomicAdd(&scnt, 1);
            sel_buf[b * HH + ((base + q) & (HH - 1))] = 1;
        } else if (f[q] > Tlo) {
            int p = atomicAdd(&ambcnt_buf[b], 1);
            if (p < AMB_CAP) amb_idx[b][p] = (unsigned int)(base + q);
        }
    }
    __syncthreads();
    if (threadIdx.x == 0 && scnt) atomicAdd(&cin_buf[b], scnt);
}

__global__ void __launch_bounds__(256) refine_kernel(const float* __restrict__ w2,
                                                     const float* __restrict__ b2) {
    int b = blockIdx.y;
    int n = min(ambcnt_buf[b], AMB_CAP);
    int wid = (blockIdx.x * blockDim.x + threadIdx.x) >> 5;
    int lid = threadIdx.x & 31;
    int nwarps = (gridDim.x * blockDim.x) >> 5;
    for (int it = wid; it < n; it += nwarps) {
        unsigned int idx = amb_idx[b][it];
        int h = idx & (HH - 1);
        const float* grow = g_buf + (size_t)b * SS * HH + (idx - h);
        const float* wrow = w2 + (size_t)h * HH;
        float s = 0.0f;
        for (int j = lid * 4; j < HH; j += 128) {
            float4 gg = *(const float4*)(grow + j);
            float4 ww = *(const float4*)(wrow + j);
            s += gg.x * ww.x + gg.y * ww.y + gg.z * ww.z + gg.w * ww.w;
        }
        #pragma unroll
        for (int o = 16; o > 0; o >>= 1)
            s += __shfl_xor_sync(0xFFFFFFFFu, s, o);
        if (lid == 0) amb_val[b][it] = s + b2[h];
    }
}

__global__ void __launch_bounds__(256) select_kernel() {
    int b = blockIdx.x;
    int n = min(ambcnt_buf[b], AMB_CAP);
    int slots = KSEL - cin_buf[b];
    if (slots < 0) slots = 0;
    if (slots > n) slots = n;
    __shared__ int red[256];

    unsigned int lo = 0u, hi = 0xFFFFFFFFu;
    while (lo < hi) {
        unsigned int mid = lo + ((hi - lo) >> 1) + 1u;
        int c = 0;
        for (int i = threadIdx.x; i < n; i += 256)
            c += (fkey(amb_val[b][i]) >= mid) ? 1 : 0;
        red[threadIdx.x] = c;
        __syncthreads();
        for (int o = 128; o > 0; o >>= 1) {
            if (threadIdx.x < o) red[threadIdx.x] += red[threadIdx.x + o];
            __syncthreads();
        }
        if (red[0] >= slots) lo = mid; else hi = mid - 1u;
        __syncthreads();
    }
    const unsigned int Kstar = lo;
    int c = 0;
    for (int i = threadIdx.x; i < n; i += 256)
        c += (fkey(amb_val[b][i]) > Kstar) ? 1 : 0;
    red[threadIdx.x] = c;
    __syncthreads();
    for (int o = 128; o > 0; o >>= 1) {
        if (threadIdx.x < o) red[threadIdx.x] += red[threadIdx.x + o];
        __syncthreads();
    }
    const int need = slots - red[0];
    for (int i = threadIdx.x; i < n; i += 256) {
        unsigned int k = fkey(amb_val[b][i]);
        bool m = false;
        if (k > Kstar) m = true;
        else if (k == Kstar) {
            int p = atomicAdd(&take_buf[b], 1);
            if (p < need) m = true;
        }
        if (m) sel_buf[b * HH + (amb_idx[b][i] & (HH - 1))] = 1;
    }
}

// ---------------- bf16 NT GEMM: cp.async (2-stage, R9 loop) + ldmatrix ------
// A,B pre-packed bf16 planes in GMEM as [rows][K/2] u32 words.
// NT: 1 / 3 / 6 -> plane count PA = 1 / 2 / 3; MMA set: (i,j) with i+j < PA.
// MT: m-subtiles per warp (4 -> 128-row CTA, 2 -> 64-row CTA).
// OUT: 0 = fp32 C; 1 = packed bf16 hi/lo; 2 = fp32 C + bf16 hi.
// SPLITZ: compile-time split-K factor. SPLITZ==1 compiles exactly like R14.
#define LDBW 20   // u32 words per SMEM row (80B stride)

template<int EPI, bool SELB, int NT, int MT, int OUT, int SPLITZ>
__global__ void __launch_bounds__(256,
    (NT == 1 && MT == 2) ? 3 : ((NT == 1 || MT == 2) ? 2 : 1))
gemm_bfx(const uint32_t* __restrict__ A0, const uint32_t* __restrict__ A1,
         const uint32_t* __restrict__ A2,
         const uint32_t* __restrict__ B0p, const uint32_t* __restrict__ B1p,
         const uint32_t* __restrict__ B2p,
         const uint32_t* __restrict__ B0c, const uint32_t* __restrict__ B1c,
         const float* __restrict__ bias_p, const float* __restrict__ bias_c,
         float* __restrict__ Cf, uint32_t* __restrict__ Ch, uint32_t* __restrict__ Cl,
         int N, int K)
{
    constexpr int PA = (NT == 1) ? 1 : (NT == 3) ? 2 : 3;
    constexpr int CTA_ROWS = MT * 32;
    constexpr int A_TILE_U = CTA_ROWS * LDBW;
    constexpr int B_TILE_U = 128 * LDBW;
    constexpr int STAGE_U  = PA * (A_TILE_U + B_TILE_U);
    constexpr int AUPT     = (CTA_ROWS * 4) / 256;

    extern __shared__ uint32_t smu[];
    const uint32_t sbase = smem_u32(smu);

    const int tid = threadIdx.x;
    const int wid = tid >> 5;
    const int lid = tid & 31;
    const int g   = lid >> 2;
    const int cth = lid & 3;
    const int wm  = wid & 1;
    const int wn  = wid >> 1;
    const int mBase = blockIdx.y * CTA_ROWS;
    const int nBase = blockIdx.x * 128;
    const int KW = K >> 1;

    // split-K (compile-time): z-slice offset into K and partial output buffer
    int koffw;
    float* Cfp;
    if constexpr (SPLITZ > 1) {
        koffw = blockIdx.z * (K / SPLITZ / 2);
        Cfp = Cf + (size_t)blockIdx.z * ((size_t)MM * DD);
    } else {
        koffw = 0;
        Cfp = Cf;
    }

    const uint32_t* Ag[3] = { A0, A1, A2 };
    const uint32_t* Bg[3] = { B0p, B1p, B2p };

    // batch = row block / SS (CTA rows never straddle a batch: 64 | 128)
    const unsigned char* selrow = SELB ? (sel_buf + (size_t)(mBase >> 7) * HH)
                                       : (const unsigned char*)0;

    float acc[MT][4][4];
    #pragma unroll
    for (int a = 0; a < MT; a++)
        #pragma unroll
        for (int b = 0; b < 4; b++)
            #pragma unroll
            for (int q = 0; q < 4; q++) acc[a][b][q] = 0.0f;

    const int nslab = (K / SPLITZ) >> 5;

    auto issue = [&](int s) {
        const int stg = s & 1;
        const int kw = koffw + s * 16;
        const uint32_t st = sbase + (uint32_t)stg * (STAGE_U * 4);
        #pragma unroll
        for (int t = 0; t < AUPT; t++) {
            const int u = t * 256 + tid;
            const int row = u >> 2, ch = u & 3;
            const uint32_t so = (uint32_t)(row * LDBW + ch * 4) * 4;
            const size_t go = (size_t)(mBase + row) * KW + kw + ch * 4;
            #pragma unroll
            for (int p = 0; p < PA; p++)
                cpasync16(st + (uint32_t)p * (A_TILE_U * 4) + so, Ag[p] + go);
        }
        #pragma unroll
        for (int t = 0; t < 2; t++) {
            const int u = t * 256 + tid;
            const int row = u >> 2, ch = u & 3;
            const int nrow = nBase + row;
            const uint32_t so = (uint32_t)(row * LDBW + ch * 4) * 4;
            const size_t go = (size_t)nrow * KW + kw + ch * 4;
            const uint32_t bb = st + (uint32_t)(PA * A_TILE_U) * 4;
            if (SELB) {
                const bool se = selrow[nrow] != 0;
                cpasync16(bb + so, (se ? B0p : B0c) + go);
                if (PA >= 2)
                    cpasync16(bb + (uint32_t)(B_TILE_U * 4) + so, (se ? B1p : B1c) + go);
            } else {
                #pragma unroll
                for (int p = 0; p < PA; p++)
                    cpasync16(bb + (uint32_t)p * (B_TILE_U * 4) + so, Bg[p] + go);
            }
        }
        asm volatile("cp.async.commit_group;" ::: "memory");
    };

    auto compute = [&](int stg) {
        const uint32_t st = sbase + (uint32_t)stg * (STAGE_U * 4);
        #pragma unroll
        for (int ks = 0; ks < 2; ks++) {
            const int pc0 = ks * 8;
            uint32_t bfr[PA][4][2];
            #pragma unroll
            for (int p = 0; p < PA; p++) {
                const uint32_t BS = st + (uint32_t)(PA * A_TILE_U + p * B_TILE_U) * 4;
                #pragma unroll
                for (int nip = 0; nip < 2; nip++) {
                    const int nb2 = wn * 32 + nip * 16;
                    const uint32_t ba = (uint32_t)((nb2 + (lid & 7) + ((lid >> 4) & 1) * 8)
                                        * LDBW + pc0) * 4 + ((lid >> 3) & 1) * 16;
                    ldmx4(bfr[p][2*nip][0], bfr[p][2*nip][1],
                          bfr[p][2*nip+1][0], bfr[p][2*nip+1][1], BS + ba);
                }
            }
            #pragma unroll
            for (int mi = 0; mi < MT; mi++) {
                const int rb = wm * (MT * 16) + mi * 16;
                const uint32_t aoff = (uint32_t)((rb + (lid & 15)) * LDBW + pc0) * 4
                                      + (lid >> 4) * 16;
                uint32_t afr[PA][4];
                #pragma unroll
                for (int p = 0; p < PA; p++)
                    ldmx4(afr[p][0], afr[p][1], afr[p][2], afr[p][3],
                          st + (uint32_t)p * (A_TILE_U * 4) + aoff);
                #pragma unroll
                for (int ni = 0; ni < 4; ni++) {
                    #pragma unroll
                    for (int o = PA - 1; o >= 0; o--)      // o = i + j
                        #pragma unroll
                        for (int i = 0; i <= o; i++)
                            mma16bf(acc[mi][ni], afr[i], bfr[o - i][ni]);
                }
            }
        }
    };

    // R9 proven loop: issue-before-wait, 2 stages, 2 syncs
    issue(0);
    for (int s = 0; s < nslab; s++) {
        if (s + 1 < nslab) {
            issue(s + 1);
            asm volatile("cp.async.wait_group 1;" ::: "memory");
        } else {
            asm volatile("cp.async.wait_group 0;" ::: "memory");
        }
        __syncthreads();
        compute(s & 1);
        __syncthreads();
    }

    #pragma unroll
    for (int mi = 0; mi < MT; mi++) {
        const int r0 = mBase + wm * (MT * 16) + mi * 16 + g;
        #pragma unroll
        for (int ni = 0; ni < 4; ni++) {
            const int col = nBase + wn * 32 + ni * 8 + 2 * cth;
            float v[4] = { acc[mi][ni][0], acc[mi][ni][1],
                           acc[mi][ni][2], acc[mi][ni][3] };
            #pragma unroll
            for (int q = 0; q < 4; q++) {
                const int cc = col + (q & 1);
                const bool se = SELB ? (selrow[cc] != 0) : false;
                v[q] = epi_apply<EPI>(v[q], cc, se, bias_p, bias_c);
            }
            if (OUT == 0 || OUT == 2) {
                *(float2*)(Cfp + (size_t)r0 * N + col)       = make_float2(v[0], v[1]);
                *(float2*)(Cfp + (size_t)(r0 + 8) * N + col) = make_float2(v[2], v[3]);
            }
            if (OUT == 1) {
                uint32_t h, l;
                pack_split_bf16(v[0], v[1], h, l);
                Ch[((size_t)r0 * N + col) >> 1] = h;
                Cl[((size_t)r0 * N + col) >> 1] = l;
                pack_split_bf16(v[2], v[3], h, l);
                Ch[((size_t)(r0 + 8) * N + col) >> 1] = h;
                Cl[((size_t)(r0 + 8) * N + col) >> 1] = l;
            }
            if (OUT == 2) {
                Ch[((size_t)r0 * N + col) >> 1]       = pack_bf16(v[0], v[1]);
                Ch[((size_t)(r0 + 8) * N + col) >> 1] = pack_bf16(v[2], v[3]);
            }
        }
    }
}

// SMEM sizes (bytes, 2 stages)
#define SMEM_G1 (2 * 3 * ((64*LDBW) + (128*LDBW)) * 4)      // NT=6, MT=2: 92KB -> 2 CTA/SM
#define SMEM_G2 (2 * 1 * ((64*LDBW) + (128*LDBW)) * 4)      // NT=1, MT=2: 30KB -> 3 CTA/SM
#define SMEM_G5 (2 * 2 * ((64*LDBW) + (128*LDBW)) * 4)      // NT=3, MT=2: 60KB -> 2 CTA/SM
#define SMEM_G6 (2 * 2 * ((64*LDBW) + (128*LDBW)) * 4)      // NT=3, MT=2: 60KB -> 2 CTA/SM

// ---------------- launch ----------------
extern "C" void kernel_launch(void* const* d_in, const int* in_sizes, int n_in,
                              void* d_out, int out_size)
{
    const float* x         = (const float*)d_in[0];   // [B,S,D]
    const float* up_prev_w = (const float*)d_in[1];   // [H,D]
    const float* up_prev_b = (const float*)d_in[2];   // [H]
    const float* up_curr_w = (const float*)d_in[3];   // [H,D]
    const float* up_curr_b = (const float*)d_in[4];   // [H]
    const float* gate_w1   = (const float*)d_in[5];   // [H,D]
    const float* gate_b1   = (const float*)d_in[6];   // [H]
    const float* gate_w2   = (const float*)d_in[7];   // [H,H]
    const float* gate_b2   = (const float*)d_in[8];   // [H]
    const float* down_w    = (const float*)d_in[9];   // [D,H]
    const float* down_b    = (const float*)d_in[10];  // [D]
    float* out = (float*)d_out;                       // [B,S,D]

    float *gp, *sp;
    uint32_t *w2h, *xh, *xm, *xl, *w1h, *w1m, *w1l;
    uint32_t *uph, *upl, *uch, *ucl, *dwh, *dwl, *ghp, *hhp, *hlp;
    cudaGetSymbolAddress((void**)&gp,  g_buf);
    cudaGetSymbolAddress((void**)&sp,  score_buf);
    cudaGetSymbolAddress((void**)&w2h, w2h_buf);
    cudaGetSymbolAddress((void**)&xh,  xh_buf);
    cudaGetSymbolAddress((void**)&xm,  xm_buf);
    cudaGetSymbolAddress((void**)&xl,  xl_buf);
    cudaGetSymbolAddress((void**)&w1h, w1h_buf);
    cudaGetSymbolAddress((void**)&w1m, w1m_buf);
    cudaGetSymbolAddress((void**)&w1l, w1l_buf);
    cudaGetSymbolAddress((void**)&uph, uph_buf);  cudaGetSymbolAddress((void**)&upl, upl_buf);
    cudaGetSymbolAddress((void**)&uch, uch_buf);  cudaGetSymbolAddress((void**)&ucl, ucl_buf);
    cudaGetSymbolAddress((void**)&dwh, dwh_buf);  cudaGetSymbolAddress((void**)&dwl, dwl_buf);
    cudaGetSymbolAddress((void**)&ghp, gh_buf);
    cudaGetSymbolAddress((void**)&hhp, hh_buf);   cudaGetSymbolAddress((void**)&hlp, hl_buf);

    cudaFuncSetAttribute((const void*)gemm_bfx<1, false, 6, 2, 2, 1>, cudaFuncAttributeMaxDynamicSharedMemorySize, SMEM_G1);
    cudaFuncSetAttribute((const void*)gemm_bfx<0, false, 1, 2, 0, 1>, cudaFuncAttributeMaxDynamicSharedMemorySize, SMEM_G2);
    cudaFuncSetAttribute((const void*)gemm_bfx<2, true, 3, 2, 1, 1>,  cudaFuncAttributeMaxDynamicSharedMemorySize, SMEM_G5);
    cudaFuncSetAttribute((const void*)gemm_bfx<3, false, 3, 2, 0, 2>, cudaFuncAttributeMaxDynamicSharedMemorySize, SMEM_G6);

    dim3 blk(256);

    // launches 1-3: decompositions (ncu -s targets our launch #4 = G1)
    decomp_split3_kernel<<<MM*DD/2/256, blk>>>((const float2*)x, xh, xm, xl, MM*DD/2);
    decomp_split3_kernel<<<HH*DD/2/256, blk>>>((const float2*)gate_w1, w1h, w1m, w1l, HH*DD/2);
    decomp_hi_kernel<<<(int)((size_t)HH*HH/2/256), blk>>>((const float2*)gate_w2, w2h, (int)((size_t)HH*HH/2));

    // 4 (ncu target): g = relu(x @ w1^T + b1) — bf16x6, 64-row CTAs, 2 CTA/SM
    gemm_bfx<1, false, 6, 2, 2, 1><<<dim3(HH/128, MM/64), blk, SMEM_G1>>>(
        xh, xm, xl, w1h, w1m, w1l, nullptr, nullptr,
        gate_b1, nullptr, gp, ghp, nullptr, HH, DD);

    // 5: scores = g @ w2^T + b2 — bf16-1, 64-row CTAs, 3 CTA/SM
    gemm_bfx<0, false, 1, 2, 0, 1><<<dim3(HH/128, MM/64), blk, SMEM_G2>>>(
        ghp, nullptr, nullptr, w2h, nullptr, nullptr, nullptr, nullptr,
        gate_b2, nullptr, sp, nullptr, nullptr, HH, HH);

    // selection machinery (4 radix passes -> exact bf16-score threshold)
    init_hist<<<8, 256>>>();
    init_misc<<<1, 32>>>();
    init_sel<<<BB * HH / 4 / 256, blk>>>();
    for (int pass = 0; pass < 4; pass++) {
        hist_pass<<<dim3(128, BB), blk>>>(pass);
        scan_pass<<<1, 256>>>();
    }
    thr_kernel<<<1, 32>>>();
    band_kernel<<<dim3(SS*HH/4/256, BB), blk>>>();
    refine_kernel<<<dim3(64, BB), blk>>>(gate_w2, gate_b2);
    select_kernel<<<BB, 256>>>();

    // decompositions for the up/down path (2-plane)
    decomp_split_kernel<<<HH*DD/2/256, blk>>>((const float2*)up_prev_w, uph, upl, HH*DD/2);
    decomp_split_kernel<<<HH*DD/2/256, blk>>>((const float2*)up_curr_w, uch, ucl, HH*DD/2);
    decomp_split_kernel<<<DD*HH/2/256, blk>>>((const float2*)down_w, dwh, dwl, DD*HH/2);

    // h = gelu(x @ mod_w^T + mod_b) — bf16x3, 64-row CTAs (x planes: xh + xm)
    gemm_bfx<2, true, 3, 2, 1, 1><<<dim3(HH/128, MM/64), blk, SMEM_G5>>>(
        xh, xm, nullptr, uph, upl, nullptr, uch, ucl,
        up_prev_b, up_curr_b, nullptr, hhp, hlp, HH, DD);

    // out = h @ down_w^T + down_b — bf16x3, split-K=2 into score_buf scratch
    gemm_bfx<3, false, 3, 2, 0, 2><<<dim3(DD/128, MM/64, 2), blk, SMEM_G6>>>(
        hhp, hlp, nullptr, dwh, dwl, nullptr, nullptr, nullptr,
        nullptr, nullptr, sp, nullptr, nullptr, DD, HH);
    combine_kernel<<<MM*DD/4/256, blk>>>(
        (const float4*)sp, (const float4*)(sp + (size_t)MM*DD), down_b,
        (float4*)out, MM*DD/4);
}